// round 16
// baseline (speedup 1.0000x reference)
#include <cuda_runtime.h>
#include <cuda_fp16.h>
#include <stdint.h>

#define NNODES 100000
#define KNN 6
#define NEDGES 600000

// ---------------- device scratch (no allocation allowed) ----------------
__device__ __half g_ya[(size_t)NNODES * 128];  // y ping
__device__ __half g_yb[(size_t)NNODES * 128];  // y pong
__device__ float4 g_ed[NEDGES];                // per-edge: (bitcast j, d0, d1, d2)

// ---------------- PTX helpers ----------------
__device__ __forceinline__ uint32_t s2u(const void* p) {
    uint32_t a;
    asm("{ .reg .u64 t; cvta.to.shared.u64 t, %1; cvt.u32.u64 %0, t; }" : "=r"(a) : "l"(p));
    return a;
}
__device__ __forceinline__ void ldm_x4(uint32_t* r, uint32_t addr) {
    asm volatile("ldmatrix.sync.aligned.m8n8.x4.shared.b16 {%0,%1,%2,%3}, [%4];"
                 : "=r"(r[0]), "=r"(r[1]), "=r"(r[2]), "=r"(r[3]) : "r"(addr));
}
__device__ __forceinline__ void mma_f16(float* c, const uint32_t* a, const uint32_t* b) {
    asm volatile("mma.sync.aligned.m16n8k16.row.col.f32.f16.f16.f32 "
                 "{%0,%1,%2,%3}, {%4,%5,%6,%7}, {%8,%9}, {%0,%1,%2,%3};"
                 : "+f"(c[0]), "+f"(c[1]), "+f"(c[2]), "+f"(c[3])
                 : "r"(a[0]), "r"(a[1]), "r"(a[2]), "r"(a[3]), "r"(b[0]), "r"(b[1]));
}
__device__ __forceinline__ uint32_t pack_h2(float a, float b) {
    __half2 v = __floats2half2_rn(a, b);
    return *(uint32_t*)&v;
}
__device__ __forceinline__ void cpa16(uint32_t saddr, const void* gaddr) {
    asm volatile("cp.async.cg.shared.global [%0], [%1], 16;" :: "r"(saddr), "l"(gaddr));
}
#define CP_COMMIT() asm volatile("cp.async.commit_group;" ::: "memory")
#define CP_WAIT0()  asm volatile("cp.async.wait_group 0;" ::: "memory")

// ============ prepE: per-edge (j, dpos) + layer-1 node GEMM (fused) ============
__global__ __launch_bounds__(256) void prepE(const float* __restrict__ pos,
                                             const int*   __restrict__ src,
                                             float4* __restrict__ ed,
                                             const float* __restrict__ W1a,
                                             const float* __restrict__ b1a,
                                             __half* __restrict__ y1)
{
    __shared__ float sW[3 * 32];
    __shared__ float sb[32];
    for (int t = threadIdx.x; t < 3 * 32; t += 256) sW[t] = W1a[t];
    for (int t = threadIdx.x; t < 32;     t += 256) sb[t] = b1a[t];
    __syncthreads();

    for (int e = blockIdx.x * 256 + threadIdx.x; e < NEDGES; e += gridDim.x * 256) {
        const int i = e / KNN;
        const int j = __ldg(&src[e]);
        float4 v;
        v.x = __int_as_float(j);
        v.y = __ldg(&pos[3 * j + 0]) - __ldg(&pos[3 * i + 0]);
        v.z = __ldg(&pos[3 * j + 1]) - __ldg(&pos[3 * i + 1]);
        v.w = __ldg(&pos[3 * j + 2]) - __ldg(&pos[3 * i + 2]);
        ed[e] = v;
    }

    const int lane = threadIdx.x & 31;
    const int gw = (blockIdx.x * 256 + threadIdx.x) >> 5;
    const int nw = (gridDim.x * 256) >> 5;
    for (int node = gw; node < NNODES; node += nw) {
        const float x0 = __ldg(&pos[3 * node]), x1 = __ldg(&pos[3 * node + 1]), x2 = __ldg(&pos[3 * node + 2]);
        float acc = sb[lane];
        acc = fmaf(x0, sW[lane], acc);
        acc = fmaf(x1, sW[32 + lane], acc);
        acc = fmaf(x2, sW[64 + lane], acc);
        y1[(size_t)node * 32 + lane] = __float2half_rn(acc);
    }
}

// ============ stage2F (unified: z aliases A(cur), 3 syncs, cp.async ed prefetch) ============
// Warp grid: WY=NWARP/WX row-warps x WX col-warps; M=16*WY rows, NC=N/WX cols/warp.
// Per tile: sync1 -> {edge-MMA(t), build(t+1), yMMA(t-1)} -> sync2 -> z-store into A(t)
//           -> sync3 -> epilogue(max+bias+relu -> hY or out).
template<int H, int N, int H2, int TH, int WX, int MINB, bool FINAL>
__global__ __launch_bounds__(TH, MINB) void stage2F(const __half* __restrict__ y,
                                                    const float4* __restrict__ ed,
                                                    const float* __restrict__ Wa,   // [(cin+3)][H]
                                                    int cin,
                                                    const float* __restrict__ Wb,   // [H][N]
                                                    const float* __restrict__ bb,
                                                    const float* __restrict__ WaN,  // [N][H2] (top rows)
                                                    const float* __restrict__ baN,
                                                    __half* __restrict__ yN,
                                                    float* __restrict__ outF)
{
    constexpr int NWARP = TH / 32;
    constexpr int WY    = NWARP / WX;
    constexpr int M     = 16 * WY;
    constexpr int EP    = (M / KNN) * KNN;
    constexpr int NODES = M / KNN;
    constexpr int SA    = H + 8;            // A/B/z row stride (halfs); N <= SA since N == H
    constexpr int SAY   = N + 8;            // hY/B2 row stride (halfs)
    constexpr int NC    = N / WX;
    constexpr int NT8W  = NC / 8;
    constexpr int KS    = H / 16;
    constexpr int G8    = H / 8;            // threads per row (8 channels each)
    constexpr int RS8   = TH / G8;
    constexpr int HYR   = ((NODES + 15) / 16) * 16;
    constexpr int AB    = M * SA * 2;
    constexpr int OFF_B  = 2 * AB;
    constexpr int OFF_WP = OFF_B + N * SA * 2;
    constexpr int OFF_BB = OFF_WP + 3 * H * 4;
    constexpr int OFF_B2 = OFF_BB + N * 4;
    constexpr int OFF_BA2= OFF_B2 + (FINAL ? 0 : H2 * SAY * 2);
    constexpr int OFF_HY = OFF_BA2 + (FINAL ? 0 : H2 * 4);
    constexpr int OFF_SED= ((OFF_HY + (FINAL ? 0 : HYR * SAY * 2)) + 15) & ~15;
    constexpr int SEDB   = EP * 16;

    extern __shared__ char smem[];
    const uint32_t sbase = s2u(smem);
    float* sWp = (float*)(smem + OFF_WP);
    float* sbb = (float*)(smem + OFF_BB);
    float* sba2= (float*)(smem + OFF_BA2);
    __half* hY = (__half*)(smem + OFF_HY);

    const int tid  = threadIdx.x;
    const int wid  = tid >> 5;
    const int lid  = tid & 31;
    const int wy   = wid % WY;
    const int wx   = wid / WY;
    const int wrow = wy * 16;
    const int wcol = wx * NC;

    // ---- block prologue ----
    const float* Wp = Wa + (size_t)cin * H;
    for (int t = tid; t < 3 * H; t += TH) sWp[t] = Wp[t];
    for (int t = tid; t < N;     t += TH) sbb[t] = bb[t];
    for (int t = tid; t < N * H; t += TH) {
        int n = t / H, k = t % H;
        *(__half*)(smem + OFF_B + (n * SA + k) * 2) = __float2half_rn(Wb[(size_t)k * N + n]);
    }
    if constexpr (!FINAL) {
        for (int t = tid; t < H2 * N; t += TH) {
            int n2 = t / N, k = t % N;
            *(__half*)(smem + OFF_B2 + (n2 * SAY + k) * 2) = __float2half_rn(WaN[(size_t)k * H2 + n2]);
        }
        for (int t = tid; t < H2; t += TH) sba2[t] = baN[t];
    }

    const int lm = lid >> 3, lr = lid & 7;
    const int a_row_off = (lm & 1) * 8 + lr;
    const int b_row_off = (lm >> 1) * 8 + lr;
    const int NT = (NEDGES + EP - 1) / EP;

    const int g8 = tid % G8;
    const int rt8 = tid / G8;
    const int cb = 8 * g8;

    auto build = [&](int sidx, int t, int buf) {
        const int ebase = t * EP;
        char* A = smem + buf * AB;
        const float4* se = (const float4*)(smem + OFF_SED + sidx * SEDB);
        #pragma unroll
        for (int r = rt8; r < M; r += RS8) {
            uint4 hv = make_uint4(0u, 0u, 0u, 0u);
            const int ge = ebase + r;
            if (r < EP && ge < NEDGES) {
                const float4 e4 = se[r];
                const int j = __float_as_int(e4.x);
                const uint4 yr = *(const uint4*)&y[(size_t)j * H + cb];
                const __half2* yh = (const __half2*)&yr;
                const float4 wx0 = *(const float4*)&sWp[cb];
                const float4 wx1 = *(const float4*)&sWp[cb + 4];
                const float4 wy0 = *(const float4*)&sWp[H + cb];
                const float4 wy1 = *(const float4*)&sWp[H + cb + 4];
                const float4 wz0 = *(const float4*)&sWp[2 * H + cb];
                const float4 wz1 = *(const float4*)&sWp[2 * H + cb + 4];
                float v0 = __low2float(yh[0]), v1 = __high2float(yh[0]);
                float v2 = __low2float(yh[1]), v3 = __high2float(yh[1]);
                float v4 = __low2float(yh[2]), v5 = __high2float(yh[2]);
                float v6 = __low2float(yh[3]), v7 = __high2float(yh[3]);
                v0 = fmaf(e4.y, wx0.x, fmaf(e4.z, wy0.x, fmaf(e4.w, wz0.x, v0)));
                v1 = fmaf(e4.y, wx0.y, fmaf(e4.z, wy0.y, fmaf(e4.w, wz0.y, v1)));
                v2 = fmaf(e4.y, wx0.z, fmaf(e4.z, wy0.z, fmaf(e4.w, wz0.z, v2)));
                v3 = fmaf(e4.y, wx0.w, fmaf(e4.z, wy0.w, fmaf(e4.w, wz0.w, v3)));
                v4 = fmaf(e4.y, wx1.x, fmaf(e4.z, wy1.x, fmaf(e4.w, wz1.x, v4)));
                v5 = fmaf(e4.y, wx1.y, fmaf(e4.z, wy1.y, fmaf(e4.w, wz1.y, v5)));
                v6 = fmaf(e4.y, wx1.z, fmaf(e4.z, wy1.z, fmaf(e4.w, wz1.z, v6)));
                v7 = fmaf(e4.y, wx1.w, fmaf(e4.z, wy1.w, fmaf(e4.w, wz1.w, v7)));
                hv.x = pack_h2(fmaxf(v0, 0.f), fmaxf(v1, 0.f));
                hv.y = pack_h2(fmaxf(v2, 0.f), fmaxf(v3, 0.f));
                hv.z = pack_h2(fmaxf(v4, 0.f), fmaxf(v5, 0.f));
                hv.w = pack_h2(fmaxf(v6, 0.f), fmaxf(v7, 0.f));
            }
            *(uint4*)(A + (r * SA + cb) * 2) = hv;
        }
    };

    auto prefetch = [&](int t, int sidx) {
        if (t < NT && tid < EP) {
            const long long ge = (long long)t * EP + tid;
            if (ge < NEDGES)
                cpa16(sbase + OFF_SED + sidx * SEDB + tid * 16, ed + ge);
        }
        CP_COMMIT();
    };

    // ---- yMMA: y_next[prev tile nodes] = hY @ WaNext^T + baNext ----
    auto ymma = [&](int ptile) {
        const int pbase = ptile * NODES;
        constexpr int MT = (NODES + 15) / 16;
        for (int task = wid; task < MT * (H2 / 16); task += NWARP) {
            const int mt = task % MT;
            const int nb = (task / MT) * 16;
            float cc[2][4] = {{0.f,0.f,0.f,0.f},{0.f,0.f,0.f,0.f}};
            #pragma unroll
            for (int k0 = 0; k0 < N; k0 += 16) {
                uint32_t a[4], b[4];
                ldm_x4(a, sbase + OFF_HY + ((mt * 16 + a_row_off) * SAY + k0 + (lm >> 1) * 8) * 2);
                ldm_x4(b, sbase + OFF_B2 + ((nb + b_row_off) * SAY + k0 + (lm & 1) * 8) * 2);
                mma_f16(cc[0], a, &b[0]);
                mma_f16(cc[1], a, &b[2]);
            }
            const int qr = lid >> 2, qc = (lid & 3) * 2;
            #pragma unroll
            for (int hh = 0; hh < 2; hh++) {
                const int col = nb + hh * 8 + qc;
                const float2 bf = *(const float2*)&sba2[col];
                const int r0 = mt * 16 + qr, r1 = r0 + 8;
                if (r0 < NODES) {
                    const int n0 = pbase + r0;
                    if (n0 < NNODES)
                        *(uint32_t*)&yN[(size_t)n0 * H2 + col] = pack_h2(cc[hh][0] + bf.x, cc[hh][1] + bf.y);
                }
                if (r1 < NODES) {
                    const int n1 = pbase + r1;
                    if (n1 < NNODES)
                        *(uint32_t*)&yN[(size_t)n1 * H2 + col] = pack_h2(cc[hh][2] + bf.x, cc[hh][3] + bf.y);
                }
            }
        }
    };

    // ---- preload: ed tiles t0, t1; build t0 ----
    const int t0 = blockIdx.x, t1 = t0 + gridDim.x;
    prefetch(t0, 0);
    prefetch(t1, 1);
    CP_WAIT0();
    __syncthreads();   // prologue + sed published
    if (t0 < NT) build(0, t0, 0);

    int cur = 0;
    int prev = -1;

    for (int tile = t0; tile < NT; tile += gridDim.x) {
        __syncthreads();   // sync1: A(cur) built & visible; prev epilogue done

        // ---- parallel section: edge-MMA(cur) + build(next) + yMMA(prev) ----
        float c[NT8W][4];
        #pragma unroll
        for (int t = 0; t < NT8W; t++)
            #pragma unroll
            for (int q = 0; q < 4; q++) c[t][q] = 0.f;
        {
            const uint32_t abase = sbase + cur * AB;
            #pragma unroll
            for (int kk = 0; kk < KS; kk++) {
                uint32_t a[4];
                ldm_x4(a, abase + ((wrow + a_row_off) * SA + kk * 16 + (lm >> 1) * 8) * 2);
                #pragma unroll
                for (int np = 0; np < NT8W / 2; np++) {
                    uint32_t b[4];
                    ldm_x4(b, sbase + OFF_B + ((wcol + np * 16 + b_row_off) * SA + kk * 16 + (lm & 1) * 8) * 2);
                    mma_f16(c[2 * np],     a, &b[0]);
                    mma_f16(c[2 * np + 1], a, &b[2]);
                }
            }
        }

        prefetch(tile + 2 * gridDim.x, cur);   // ed for tile+2 -> sed[cur]
        const int ntl = tile + gridDim.x;
        if (ntl < NT) build(cur ^ 1, ntl, cur ^ 1);
        if constexpr (!FINAL) { if (prev >= 0) ymma(prev); }

        CP_WAIT0();
        __syncthreads();   // sync2: MMA readers of A(cur) done; builds done; sed arrived

        // ---- z-store into A(cur) region (fp16, row stride SA) ----
        __half* zz = (__half*)(smem + cur * AB);
        {
            const int qr = lid >> 2, qc = (lid & 3) * 2;
            #pragma unroll
            for (int t = 0; t < NT8W; t++) {
                const int col = wcol + t * 8 + qc;
                *(uint32_t*)&zz[(wrow + qr) * SA + col]     = pack_h2(c[t][0], c[t][1]);
                *(uint32_t*)&zz[(wrow + qr + 8) * SA + col] = pack_h2(c[t][2], c[t][3]);
            }
        }
        __syncthreads();   // sync3: z complete

        // ---- 6-row max + bias + relu -> hY (or out) ----
        for (int t = tid; t < NODES * (N / 2); t += TH) {
            const int g = t / (N / 2), c2 = (t % (N / 2)) * 2;
            const int node = tile * NODES + g;
            const __half2* zp = (const __half2*)(zz + (6 * g) * SA + c2);
            constexpr int S2 = SA / 2;
            __half2 m = zp[0];
            m = __hmax2(m, zp[S2]);
            m = __hmax2(m, zp[2 * S2]);
            m = __hmax2(m, zp[3 * S2]);
            m = __hmax2(m, zp[4 * S2]);
            m = __hmax2(m, zp[5 * S2]);
            const float2 bf = *(const float2*)&sbb[c2];
            const float r0 = fmaxf(__low2float(m)  + bf.x, 0.f);
            const float r1 = fmaxf(__high2float(m) + bf.y, 0.f);
            if constexpr (FINAL) {
                if (node < NNODES)
                    *(float2*)&outF[(size_t)node * N + c2] = make_float2(r0, r1);
            } else {
                hY[g * SAY + c2]     = __float2half_rn(r0);
                hY[g * SAY + c2 + 1] = __float2half_rn(r1);
            }
        }
        prev = tile;
        cur ^= 1;
    }

    if constexpr (!FINAL) {
        if (prev >= 0) {
            __syncthreads();   // final epilogue's hY writes visible
            ymma(prev);
        }
    }
}

template<int H, int N, int H2, int TH, int WX, bool FINAL>
static constexpr int smemF() {
    constexpr int NWARP = TH / 32;
    constexpr int M   = 16 * (NWARP / WX);
    constexpr int EP  = (M / KNN) * KNN;
    constexpr int NODES = M / KNN;
    constexpr int HYR = ((NODES + 15) / 16) * 16;
    constexpr int SA  = H + 8;
    constexpr int SAY = N + 8;
    int s = 2 * M * SA * 2 + N * SA * 2 + 3 * H * 4 + N * 4;
    if (!FINAL) s += H2 * SAY * 2 + H2 * 4 + HYR * SAY * 2;
    s = (s + 15) & ~15;
    s += 2 * EP * 16;
    return s + 64;
}

// ---------------- host ----------------
extern "C" void kernel_launch(void* const* d_in, const int* in_sizes, int n_in,
                              void* d_out, int out_size)
{
    const float* pos = (const float*)d_in[0];
    const int*   src = (const int*)d_in[1];   // row 0 of edge_index
    const float* W1a = (const float*)d_in[2];
    const float* b1a = (const float*)d_in[3];
    const float* W1b = (const float*)d_in[4];
    const float* b1b = (const float*)d_in[5];
    const float* W2a = (const float*)d_in[6];
    const float* b2a = (const float*)d_in[7];
    const float* W2b = (const float*)d_in[8];
    const float* b2b = (const float*)d_in[9];
    const float* W3a = (const float*)d_in[10];
    const float* b3a = (const float*)d_in[11];
    const float* W3b = (const float*)d_in[12];
    const float* b3b = (const float*)d_in[13];
    float* out = (float*)d_out;

    __half *ya, *yb;
    float4* ed;
    cudaGetSymbolAddress((void**)&ya, g_ya);
    cudaGetSymbolAddress((void**)&yb, g_yb);
    cudaGetSymbolAddress((void**)&ed, g_ed);

    constexpr int S1 = smemF<32, 32, 64, 512, 1, false>();     // ~61 KB  (2 CTAs/SM)
    constexpr int S2 = smemF<64, 64, 128, 512, 2, false>();    // ~112 KB (2 CTAs/SM)
    constexpr int S3 = smemF<128, 128, 16, 512, 2, true>();    // ~111 KB (2 CTAs/SM)
    cudaFuncSetAttribute(stage2F<32, 32, 64, 512, 1, 2, false>,   cudaFuncAttributeMaxDynamicSharedMemorySize, S1);
    cudaFuncSetAttribute(stage2F<64, 64, 128, 512, 2, 2, false>,  cudaFuncAttributeMaxDynamicSharedMemorySize, S2);
    cudaFuncSetAttribute(stage2F<128, 128, 16, 512, 2, 2, true>,  cudaFuncAttributeMaxDynamicSharedMemorySize, S3);

    // prep: edge table + layer-1 node GEMM (y1 -> ya)
    prepE<<<1024, 256>>>(pos, src, ed, W1a, b1a, ya);

    // layer 1: edge GEMM (32) + max + fused node GEMM for layer 2 (y2 -> yb)
    stage2F<32, 32, 64, 512, 1, 2, false><<<296, 512, S1>>>(ya, ed, W1a, 3, W1b, b1b, W2a, b2a, yb, nullptr);

    // layer 2: edge GEMM (64) + max + fused node GEMM for layer 3 (y3 -> ya)
    stage2F<64, 64, 128, 512, 2, 2, false><<<296, 512, S2>>>(yb, ed, W2a, 32, W2b, b2b, W3a, b3a, ya, nullptr);

    // layer 3: edge GEMM (128) + max -> final out (fp32)
    stage2F<128, 128, 16, 512, 2, 2, true><<<296, 512, S3>>>(ya, ed, W3a, 64, W3b, b3b, nullptr, nullptr, nullptr, out);
}

// round 17
// speedup vs baseline: 1.0182x; 1.0182x over previous
#include <cuda_runtime.h>
#include <cuda_fp16.h>
#include <stdint.h>

#define NNODES 100000
#define KNN 6
#define NEDGES 600000

// ---------------- device scratch (no allocation allowed) ----------------
__device__ __half g_ya[(size_t)NNODES * 128];  // y ping
__device__ __half g_yb[(size_t)NNODES * 128];  // y pong
__device__ float4 g_ed[NEDGES];                // per-edge: (bitcast j, d0, d1, d2)

// ---------------- PTX helpers ----------------
__device__ __forceinline__ uint32_t s2u(const void* p) {
    uint32_t a;
    asm("{ .reg .u64 t; cvta.to.shared.u64 t, %1; cvt.u32.u64 %0, t; }" : "=r"(a) : "l"(p));
    return a;
}
__device__ __forceinline__ void ldm_x4(uint32_t* r, uint32_t addr) {
    asm volatile("ldmatrix.sync.aligned.m8n8.x4.shared.b16 {%0,%1,%2,%3}, [%4];"
                 : "=r"(r[0]), "=r"(r[1]), "=r"(r[2]), "=r"(r[3]) : "r"(addr));
}
__device__ __forceinline__ void mma_f16(float* c, const uint32_t* a, const uint32_t* b) {
    asm volatile("mma.sync.aligned.m16n8k16.row.col.f32.f16.f16.f32 "
                 "{%0,%1,%2,%3}, {%4,%5,%6,%7}, {%8,%9}, {%0,%1,%2,%3};"
                 : "+f"(c[0]), "+f"(c[1]), "+f"(c[2]), "+f"(c[3])
                 : "r"(a[0]), "r"(a[1]), "r"(a[2]), "r"(a[3]), "r"(b[0]), "r"(b[1]));
}
__device__ __forceinline__ uint32_t pack_h2(float a, float b) {
    __half2 v = __floats2half2_rn(a, b);
    return *(uint32_t*)&v;
}
__device__ __forceinline__ void cpa16(uint32_t saddr, const void* gaddr) {
    asm volatile("cp.async.cg.shared.global [%0], [%1], 16;" :: "r"(saddr), "l"(gaddr));
}
#define CP_COMMIT() asm volatile("cp.async.commit_group;" ::: "memory")
#define CP_WAIT0()  asm volatile("cp.async.wait_group 0;" ::: "memory")

// ============ prepE: per-edge (j, dpos) + layer-1 node GEMM (fused) ============
__global__ __launch_bounds__(256) void prepE(const float* __restrict__ pos,
                                             const int*   __restrict__ src,
                                             float4* __restrict__ ed,
                                             const float* __restrict__ W1a,
                                             const float* __restrict__ b1a,
                                             __half* __restrict__ y1)
{
    __shared__ float sW[3 * 32];
    __shared__ float sb[32];
    for (int t = threadIdx.x; t < 3 * 32; t += 256) sW[t] = W1a[t];
    for (int t = threadIdx.x; t < 32;     t += 256) sb[t] = b1a[t];
    __syncthreads();

    for (int e = blockIdx.x * 256 + threadIdx.x; e < NEDGES; e += gridDim.x * 256) {
        const int i = e / KNN;
        const int j = __ldg(&src[e]);
        float4 v;
        v.x = __int_as_float(j);
        v.y = __ldg(&pos[3 * j + 0]) - __ldg(&pos[3 * i + 0]);
        v.z = __ldg(&pos[3 * j + 1]) - __ldg(&pos[3 * i + 1]);
        v.w = __ldg(&pos[3 * j + 2]) - __ldg(&pos[3 * i + 2]);
        ed[e] = v;
    }

    const int lane = threadIdx.x & 31;
    const int gw = (blockIdx.x * 256 + threadIdx.x) >> 5;
    const int nw = (gridDim.x * 256) >> 5;
    for (int node = gw; node < NNODES; node += nw) {
        const float x0 = __ldg(&pos[3 * node]), x1 = __ldg(&pos[3 * node + 1]), x2 = __ldg(&pos[3 * node + 2]);
        float acc = sb[lane];
        acc = fmaf(x0, sW[lane], acc);
        acc = fmaf(x1, sW[32 + lane], acc);
        acc = fmaf(x2, sW[64 + lane], acc);
        y1[(size_t)node * 32 + lane] = __float2half_rn(acc);
    }
}

// ============ stage2F (z aliases A(cur), 3 syncs, cp.async ed prefetch, MI m-subtiles) ======
// Warp grid: WY row-warps x WX col-warps; each warp owns MI 16-row m-subtiles x NC cols.
// M = 16*WY*MI. B fragment loaded once per (k,np), reused across MI A fragments.
template<int H, int N, int H2, int TH, int WX, int MI, int MINB, bool FINAL>
__global__ __launch_bounds__(TH, MINB) void stage2F(const __half* __restrict__ y,
                                                    const float4* __restrict__ ed,
                                                    const float* __restrict__ Wa,   // [(cin+3)][H]
                                                    int cin,
                                                    const float* __restrict__ Wb,   // [H][N]
                                                    const float* __restrict__ bb,
                                                    const float* __restrict__ WaN,  // [N][H2] (top rows)
                                                    const float* __restrict__ baN,
                                                    __half* __restrict__ yN,
                                                    float* __restrict__ outF)
{
    constexpr int NWARP = TH / 32;
    constexpr int WY    = NWARP / WX;
    constexpr int M     = 16 * WY * MI;
    constexpr int EP    = (M / KNN) * KNN;
    constexpr int NODES = M / KNN;
    constexpr int SA    = H + 8;            // A/B/z row stride (halfs); N <= SA since N == H
    constexpr int SAY   = N + 8;            // hY/B2 row stride (halfs)
    constexpr int NC    = N / WX;
    constexpr int NT8W  = NC / 8;
    constexpr int KS    = H / 16;
    constexpr int G8    = H / 8;            // threads per row (8 channels each)
    constexpr int RS8   = TH / G8;
    constexpr int HYR   = ((NODES + 15) / 16) * 16;
    constexpr int AB    = M * SA * 2;
    constexpr int OFF_B  = 2 * AB;
    constexpr int OFF_WP = OFF_B + N * SA * 2;
    constexpr int OFF_BB = OFF_WP + 3 * H * 4;
    constexpr int OFF_B2 = OFF_BB + N * 4;
    constexpr int OFF_BA2= OFF_B2 + (FINAL ? 0 : H2 * SAY * 2);
    constexpr int OFF_HY = OFF_BA2 + (FINAL ? 0 : H2 * 4);
    constexpr int OFF_SED= ((OFF_HY + (FINAL ? 0 : HYR * SAY * 2)) + 15) & ~15;
    constexpr int SEDB   = EP * 16;

    extern __shared__ char smem[];
    const uint32_t sbase = s2u(smem);
    float* sWp = (float*)(smem + OFF_WP);
    float* sbb = (float*)(smem + OFF_BB);
    float* sba2= (float*)(smem + OFF_BA2);
    __half* hY = (__half*)(smem + OFF_HY);

    const int tid  = threadIdx.x;
    const int wid  = tid >> 5;
    const int lid  = tid & 31;
    const int wy   = wid % WY;
    const int wx   = wid / WY;
    const int wcol = wx * NC;

    // ---- block prologue ----
    const float* Wp = Wa + (size_t)cin * H;
    for (int t = tid; t < 3 * H; t += TH) sWp[t] = Wp[t];
    for (int t = tid; t < N;     t += TH) sbb[t] = bb[t];
    for (int t = tid; t < N * H; t += TH) {
        int n = t / H, k = t % H;
        *(__half*)(smem + OFF_B + (n * SA + k) * 2) = __float2half_rn(Wb[(size_t)k * N + n]);
    }
    if constexpr (!FINAL) {
        for (int t = tid; t < H2 * N; t += TH) {
            int n2 = t / N, k = t % N;
            *(__half*)(smem + OFF_B2 + (n2 * SAY + k) * 2) = __float2half_rn(WaN[(size_t)k * H2 + n2]);
        }
        for (int t = tid; t < H2; t += TH) sba2[t] = baN[t];
    }

    const int lm = lid >> 3, lr = lid & 7;
    const int a_row_off = (lm & 1) * 8 + lr;
    const int b_row_off = (lm >> 1) * 8 + lr;
    const int NT = (NEDGES + EP - 1) / EP;

    const int g8 = tid % G8;
    const int rt8 = tid / G8;
    const int cb = 8 * g8;

    auto build = [&](int sidx, int t, int buf) {
        const int ebase = t * EP;
        char* A = smem + buf * AB;
        const float4* se = (const float4*)(smem + OFF_SED + sidx * SEDB);
        #pragma unroll
        for (int r = rt8; r < M; r += RS8) {
            uint4 hv = make_uint4(0u, 0u, 0u, 0u);
            const int ge = ebase + r;
            if (r < EP && ge < NEDGES) {
                const float4 e4 = se[r];
                const int j = __float_as_int(e4.x);
                const uint4 yr = *(const uint4*)&y[(size_t)j * H + cb];
                const __half2* yh = (const __half2*)&yr;
                const float4 wx0 = *(const float4*)&sWp[cb];
                const float4 wx1 = *(const float4*)&sWp[cb + 4];
                const float4 wy0 = *(const float4*)&sWp[H + cb];
                const float4 wy1 = *(const float4*)&sWp[H + cb + 4];
                const float4 wz0 = *(const float4*)&sWp[2 * H + cb];
                const float4 wz1 = *(const float4*)&sWp[2 * H + cb + 4];
                float v0 = __low2float(yh[0]), v1 = __high2float(yh[0]);
                float v2 = __low2float(yh[1]), v3 = __high2float(yh[1]);
                float v4 = __low2float(yh[2]), v5 = __high2float(yh[2]);
                float v6 = __low2float(yh[3]), v7 = __high2float(yh[3]);
                v0 = fmaf(e4.y, wx0.x, fmaf(e4.z, wy0.x, fmaf(e4.w, wz0.x, v0)));
                v1 = fmaf(e4.y, wx0.y, fmaf(e4.z, wy0.y, fmaf(e4.w, wz0.y, v1)));
                v2 = fmaf(e4.y, wx0.z, fmaf(e4.z, wy0.z, fmaf(e4.w, wz0.z, v2)));
                v3 = fmaf(e4.y, wx0.w, fmaf(e4.z, wy0.w, fmaf(e4.w, wz0.w, v3)));
                v4 = fmaf(e4.y, wx1.x, fmaf(e4.z, wy1.x, fmaf(e4.w, wz1.x, v4)));
                v5 = fmaf(e4.y, wx1.y, fmaf(e4.z, wy1.y, fmaf(e4.w, wz1.y, v5)));
                v6 = fmaf(e4.y, wx1.z, fmaf(e4.z, wy1.z, fmaf(e4.w, wz1.z, v6)));
                v7 = fmaf(e4.y, wx1.w, fmaf(e4.z, wy1.w, fmaf(e4.w, wz1.w, v7)));
                hv.x = pack_h2(fmaxf(v0, 0.f), fmaxf(v1, 0.f));
                hv.y = pack_h2(fmaxf(v2, 0.f), fmaxf(v3, 0.f));
                hv.z = pack_h2(fmaxf(v4, 0.f), fmaxf(v5, 0.f));
                hv.w = pack_h2(fmaxf(v6, 0.f), fmaxf(v7, 0.f));
            }
            *(uint4*)(A + (r * SA + cb) * 2) = hv;
        }
    };

    auto prefetch = [&](int t, int sidx) {
        if (t < NT && tid < EP) {
            const long long ge = (long long)t * EP + tid;
            if (ge < NEDGES)
                cpa16(sbase + OFF_SED + sidx * SEDB + tid * 16, ed + ge);
        }
        CP_COMMIT();
    };

    // ---- yMMA: y_next[prev tile nodes] = hY @ WaNext^T + baNext ----
    auto ymma = [&](int ptile) {
        const int pbase = ptile * NODES;
        constexpr int MT = (NODES + 15) / 16;
        for (int task = wid; task < MT * (H2 / 16); task += NWARP) {
            const int mt = task % MT;
            const int nb = (task / MT) * 16;
            float cc[2][4] = {{0.f,0.f,0.f,0.f},{0.f,0.f,0.f,0.f}};
            #pragma unroll
            for (int k0 = 0; k0 < N; k0 += 16) {
                uint32_t a[4], b[4];
                ldm_x4(a, sbase + OFF_HY + ((mt * 16 + a_row_off) * SAY + k0 + (lm >> 1) * 8) * 2);
                ldm_x4(b, sbase + OFF_B2 + ((nb + b_row_off) * SAY + k0 + (lm & 1) * 8) * 2);
                mma_f16(cc[0], a, &b[0]);
                mma_f16(cc[1], a, &b[2]);
            }
            const int qr = lid >> 2, qc = (lid & 3) * 2;
            #pragma unroll
            for (int hh = 0; hh < 2; hh++) {
                const int col = nb + hh * 8 + qc;
                const float2 bf = *(const float2*)&sba2[col];
                const int r0 = mt * 16 + qr, r1 = r0 + 8;
                if (r0 < NODES) {
                    const int n0 = pbase + r0;
                    if (n0 < NNODES)
                        *(uint32_t*)&yN[(size_t)n0 * H2 + col] = pack_h2(cc[hh][0] + bf.x, cc[hh][1] + bf.y);
                }
                if (r1 < NODES) {
                    const int n1 = pbase + r1;
                    if (n1 < NNODES)
                        *(uint32_t*)&yN[(size_t)n1 * H2 + col] = pack_h2(cc[hh][2] + bf.x, cc[hh][3] + bf.y);
                }
            }
        }
    };

    // ---- preload: ed tiles t0, t1; build t0 ----
    const int t0 = blockIdx.x, t1 = t0 + gridDim.x;
    prefetch(t0, 0);
    prefetch(t1, 1);
    CP_WAIT0();
    __syncthreads();   // prologue + sed published
    if (t0 < NT) build(0, t0, 0);

    int cur = 0;
    int prev = -1;

    for (int tile = t0; tile < NT; tile += gridDim.x) {
        __syncthreads();   // sync1: A(cur) built & visible; prev epilogue done

        // ---- parallel section: edge-MMA(cur) + build(next) + yMMA(prev) ----
        float c[MI][NT8W][4];
        #pragma unroll
        for (int mi = 0; mi < MI; mi++)
            #pragma unroll
            for (int t = 0; t < NT8W; t++)
                #pragma unroll
                for (int q = 0; q < 4; q++) c[mi][t][q] = 0.f;
        {
            const uint32_t abase = sbase + cur * AB;
            #pragma unroll
            for (int kk = 0; kk < KS; kk++) {
                uint32_t a[MI][4];
                #pragma unroll
                for (int mi = 0; mi < MI; mi++)
                    ldm_x4(a[mi], abase + (((wy * MI + mi) * 16 + a_row_off) * SA + kk * 16 + (lm >> 1) * 8) * 2);
                #pragma unroll
                for (int np = 0; np < NT8W / 2; np++) {
                    uint32_t b[4];
                    ldm_x4(b, sbase + OFF_B + ((wcol + np * 16 + b_row_off) * SA + kk * 16 + (lm & 1) * 8) * 2);
                    #pragma unroll
                    for (int mi = 0; mi < MI; mi++) {
                        mma_f16(c[mi][2 * np],     a[mi], &b[0]);
                        mma_f16(c[mi][2 * np + 1], a[mi], &b[2]);
                    }
                }
            }
        }

        prefetch(tile + 2 * gridDim.x, cur);   // ed for tile+2 -> sed[cur]
        const int ntl = tile + gridDim.x;
        if (ntl < NT) build(cur ^ 1, ntl, cur ^ 1);
        if constexpr (!FINAL) { if (prev >= 0) ymma(prev); }

        CP_WAIT0();
        __syncthreads();   // sync2: MMA readers of A(cur) done; builds done; sed arrived

        // ---- z-store into A(cur) region (fp16, row stride SA) ----
        __half* zz = (__half*)(smem + cur * AB);
        {
            const int qr = lid >> 2, qc = (lid & 3) * 2;
            #pragma unroll
            for (int mi = 0; mi < MI; mi++) {
                const int rbase = (wy * MI + mi) * 16;
                #pragma unroll
                for (int t = 0; t < NT8W; t++) {
                    const int col = wcol + t * 8 + qc;
                    *(uint32_t*)&zz[(rbase + qr) * SA + col]     = pack_h2(c[mi][t][0], c[mi][t][1]);
                    *(uint32_t*)&zz[(rbase + qr + 8) * SA + col] = pack_h2(c[mi][t][2], c[mi][t][3]);
                }
            }
        }
        __syncthreads();   // sync3: z complete

        // ---- 6-row max + bias + relu (8 cols per thread, uint4 LDS) ----
        for (int t = tid; t < NODES * (N / 8); t += TH) {
            const int g = t / (N / 8), c8 = (t % (N / 8)) * 8;
            const int node = tile * NODES + g;
            const __half* zp = zz + (6 * g) * SA + c8;
            uint4 r = *(const uint4*)zp;
            __half2 m0 = *(__half2*)&r.x, m1 = *(__half2*)&r.y;
            __half2 m2 = *(__half2*)&r.z, m3 = *(__half2*)&r.w;
            #pragma unroll
            for (int e = 1; e < 6; e++) {
                uint4 q = *(const uint4*)(zp + e * SA);
                m0 = __hmax2(m0, *(__half2*)&q.x);
                m1 = __hmax2(m1, *(__half2*)&q.y);
                m2 = __hmax2(m2, *(__half2*)&q.z);
                m3 = __hmax2(m3, *(__half2*)&q.w);
            }
            const float4 b0 = *(const float4*)&sbb[c8];
            const float4 b1 = *(const float4*)&sbb[c8 + 4];
            float v0 = fmaxf(__low2float(m0)  + b0.x, 0.f);
            float v1 = fmaxf(__high2float(m0) + b0.y, 0.f);
            float v2 = fmaxf(__low2float(m1)  + b0.z, 0.f);
            float v3 = fmaxf(__high2float(m1) + b0.w, 0.f);
            float v4 = fmaxf(__low2float(m2)  + b1.x, 0.f);
            float v5 = fmaxf(__high2float(m2) + b1.y, 0.f);
            float v6 = fmaxf(__low2float(m3)  + b1.z, 0.f);
            float v7 = fmaxf(__high2float(m3) + b1.w, 0.f);
            if constexpr (FINAL) {
                if (node < NNODES) {
                    *(float4*)&outF[(size_t)node * N + c8]     = make_float4(v0, v1, v2, v3);
                    *(float4*)&outF[(size_t)node * N + c8 + 4] = make_float4(v4, v5, v6, v7);
                }
            } else {
                uint4 hv;
                hv.x = pack_h2(v0, v1); hv.y = pack_h2(v2, v3);
                hv.z = pack_h2(v4, v5); hv.w = pack_h2(v6, v7);
                *(uint4*)&hY[g * SAY + c8] = hv;
            }
        }
        prev = tile;
        cur ^= 1;
    }

    if constexpr (!FINAL) {
        if (prev >= 0) {
            __syncthreads();   // final epilogue's hY writes visible
            ymma(prev);
        }
    }
}

template<int H, int N, int H2, int TH, int WX, int MI, bool FINAL>
static constexpr int smemF() {
    constexpr int NWARP = TH / 32;
    constexpr int M   = 16 * (NWARP / WX) * MI;
    constexpr int EP  = (M / KNN) * KNN;
    constexpr int NODES = M / KNN;
    constexpr int HYR = ((NODES + 15) / 16) * 16;
    constexpr int SA  = H + 8;
    constexpr int SAY = N + 8;
    int s = 2 * M * SA * 2 + N * SA * 2 + 3 * H * 4 + N * 4;
    if (!FINAL) s += H2 * SAY * 2 + H2 * 4 + HYR * SAY * 2;
    s = (s + 15) & ~15;
    s += 2 * EP * 16;
    return s + 64;
}

// ---------------- host ----------------
extern "C" void kernel_launch(void* const* d_in, const int* in_sizes, int n_in,
                              void* d_out, int out_size)
{
    const float* pos = (const float*)d_in[0];
    const int*   src = (const int*)d_in[1];   // row 0 of edge_index
    const float* W1a = (const float*)d_in[2];
    const float* b1a = (const float*)d_in[3];
    const float* W1b = (const float*)d_in[4];
    const float* b1b = (const float*)d_in[5];
    const float* W2a = (const float*)d_in[6];
    const float* b2a = (const float*)d_in[7];
    const float* W2b = (const float*)d_in[8];
    const float* b2b = (const float*)d_in[9];
    const float* W3a = (const float*)d_in[10];
    const float* b3a = (const float*)d_in[11];
    const float* W3b = (const float*)d_in[12];
    const float* b3b = (const float*)d_in[13];
    float* out = (float*)d_out;

    __half *ya, *yb;
    float4* ed;
    cudaGetSymbolAddress((void**)&ya, g_ya);
    cudaGetSymbolAddress((void**)&yb, g_yb);
    cudaGetSymbolAddress((void**)&ed, g_ed);

    constexpr int S1 = smemF<32, 32, 64, 512, 1, 1, false>();     // ~61 KB  (2 CTAs/SM)
    constexpr int S2 = smemF<64, 64, 128, 512, 2, 1, false>();    // ~112 KB (2 CTAs/SM)
    constexpr int S3 = smemF<128, 128, 16, 512, 4, 2, true>();    // ~111 KB (2 CTAs/SM)
    cudaFuncSetAttribute(stage2F<32, 32, 64, 512, 1, 1, 2, false>,   cudaFuncAttributeMaxDynamicSharedMemorySize, S1);
    cudaFuncSetAttribute(stage2F<64, 64, 128, 512, 2, 1, 2, false>,  cudaFuncAttributeMaxDynamicSharedMemorySize, S2);
    cudaFuncSetAttribute(stage2F<128, 128, 16, 512, 4, 2, 2, true>,  cudaFuncAttributeMaxDynamicSharedMemorySize, S3);

    // prep: edge table + layer-1 node GEMM (y1 -> ya)
    prepE<<<1024, 256>>>(pos, src, ed, W1a, b1a, ya);

    // layer 1: edge GEMM (32) + max + fused node GEMM for layer 2 (y2 -> yb)
    stage2F<32, 32, 64, 512, 1, 1, 2, false><<<296, 512, S1>>>(ya, ed, W1a, 3, W1b, b1b, W2a, b2a, yb, nullptr);

    // layer 2: edge GEMM (64) + max + fused node GEMM for layer 3 (y3 -> ya)
    stage2F<64, 64, 128, 512, 2, 1, 2, false><<<296, 512, S2>>>(yb, ed, W2a, 32, W2b, b2b, W3a, b3a, ya, nullptr);

    // layer 3: edge GEMM (128) + max -> final out (fp32); WX=4, MI=2 (M=128)
    stage2F<128, 128, 16, 512, 4, 2, 2, true><<<296, 512, S3>>>(ya, ed, W3a, 64, W3b, b3b, nullptr, nullptr, nullptr, out);
}